// round 14
// baseline (speedup 1.0000x reference)
#include <cuda_runtime.h>
#include <cuda_fp16.h>
#include <cstdint>

#define Hh 768
#define Ff 32
#define Tt 256
#define HF 800
#define BSr 1024
#define NU 4096
#define Cc 16
#define WDd 64
#define Ss 256

// ------------------------------- scratch (device globals)
__device__ __align__(256) __half g_x   [BSr * HF];
__device__ __align__(256) __half g_sW16[HF * Tt];
__device__ __align__(256) __half g_eW16[HF * Tt];
__device__ __align__(256) __half g_U16 [Tt * NU];
__device__ __align__(256) __half g_s16 [BSr * Tt];
__device__ __align__(256) __half g_e16 [BSr * Tt];
__device__ __align__(256) __half g_sU  [BSr * NU];
__device__ float g_prS[2][BSr * Cc];
__device__ float g_prE[2][BSr * Cc];
__device__ float g_whWw[Ss * Ss * Cc];

// ------------------------------- PTX helpers
__device__ __forceinline__ uint32_t smem_u32(const void* p) {
    uint32_t a;
    asm("{ .reg .u64 t; cvta.to.shared.u64 t, %1; cvt.u32.u64 %0, t; }" : "=r"(a) : "l"(p));
    return a;
}
__device__ __forceinline__ void cpa16(uint32_t dst, const void* src) {
    asm volatile("cp.async.cg.shared.global [%0], [%1], 16;" :: "r"(dst), "l"(src));
}
#define CP_COMMIT() asm volatile("cp.async.commit_group;" ::: "memory")
#define CP_WAIT(n)  asm volatile("cp.async.wait_group %0;" :: "n"(n) : "memory")

__device__ __forceinline__ void ldsm4(uint32_t& r0, uint32_t& r1, uint32_t& r2, uint32_t& r3, uint32_t a) {
    asm volatile("ldmatrix.sync.aligned.m8n8.x4.shared.b16 {%0,%1,%2,%3}, [%4];"
                 : "=r"(r0), "=r"(r1), "=r"(r2), "=r"(r3) : "r"(a));
}
__device__ __forceinline__ void ldsm4t(uint32_t& r0, uint32_t& r1, uint32_t& r2, uint32_t& r3, uint32_t a) {
    asm volatile("ldmatrix.sync.aligned.m8n8.x4.trans.shared.b16 {%0,%1,%2,%3}, [%4];"
                 : "=r"(r0), "=r"(r1), "=r"(r2), "=r"(r3) : "r"(a));
}
__device__ __forceinline__ void mma_f16(float* c, const uint32_t* a, const uint32_t* b) {
    asm volatile("mma.sync.aligned.m16n8k16.row.col.f32.f16.f16.f32 "
                 "{%0,%1,%2,%3},{%4,%5,%6,%7},{%8,%9},{%0,%1,%2,%3};"
                 : "+f"(c[0]), "+f"(c[1]), "+f"(c[2]), "+f"(c[3])
                 : "r"(a[0]), "r"(a[1]), "r"(a[2]), "r"(a[3]), "r"(b[0]), "r"(b[1]));
}
__device__ __forceinline__ uint32_t pkh2(float a, float b) {
    __half2 t = __floats2half2_rn(a, b);
    return *reinterpret_cast<uint32_t*>(&t);
}

constexpr int STG = 4;

// ---------------------------------------------------------------------------
// Big GEMMs at the legacy-mma issue ceiling: MT=128, occ 2.
// EPI: 1 = sU, 2 = pre (+ fused FFN terms; transposed C staging)
// ---------------------------------------------------------------------------
template<int EPI, bool BT>
__global__ void __launch_bounds__(256, 2)
mma_gemm(const float* __restrict__ p0, float* __restrict__ outp, int K)
{
    constexpr int MT = 128;
    constexpr int TA = MT * 80;
    constexpr int TB = BT ? 32 * 272 : 128 * 80;
    constexpr int STAGE = TA + TB;
    constexpr int MI = 4;

    extern __shared__ char sm[];
    const uint32_t smb = smem_u32(sm);
    const int tid = threadIdx.x, lane = tid & 31, w = tid >> 5;
    const int wm = w >> 2, wn = w & 3;

    int m0, n0;
    const __half *A, *Bg;
    int lda, ldn, bn0 = 0;
    if (EPI == 1) {
        m0 = blockIdx.y * MT; n0 = blockIdx.x * 128; lda = Tt;
        A = g_s16 + (size_t)m0 * Tt;
        Bg = g_U16; bn0 = n0; ldn = NU;
    } else {
        const int b = blockIdx.z;
        m0 = b * 4096 + blockIdx.y * MT; n0 = blockIdx.x * 128; lda = Tt;
        A = g_sU + (size_t)m0 * Tt;
        Bg = g_e16 + (size_t)b * Ss * Tt + (size_t)n0 * Tt;
        ldn = Tt;
    }

    float acc[MI][4][4] = {};
    const int nk = K / 32;

    auto load_stage = [&](int st, int kb) {
        const uint32_t sb = smb + st * STAGE;
        const int kc = kb * 32;
#pragma unroll
        for (int i = tid; i < MT * 4; i += 256) {
            const int row = i >> 2, ch = i & 3;
            cpa16(sb + row * 80 + ch * 16, A + (size_t)row * lda + kc + ch * 8);
        }
        if (BT) {
#pragma unroll
            for (int i = tid; i < 512; i += 256) {
                const int row = i >> 4, ch = i & 15;
                cpa16(sb + TA + row * 272 + ch * 16,
                      Bg + (size_t)(kc + row) * ldn + bn0 + ch * 8);
            }
        } else {
#pragma unroll
            for (int i = tid; i < 512; i += 256) {
                const int row = i >> 2, ch = i & 3;
                cpa16(sb + TA + row * 80 + ch * 16,
                      Bg + (size_t)row * ldn + kc + ch * 8);
            }
        }
    };

#pragma unroll
    for (int s = 0; s < STG - 1; s++) {
        if (s < nk) load_stage(s, s);
        CP_COMMIT();
    }

    for (int kb = 0; kb < nk; kb++) {
        CP_WAIT(STG - 2);
        __syncthreads();
        const int nx = kb + STG - 1;
        if (nx < nk) load_stage(nx % STG, nx);
        CP_COMMIT();

        const uint32_t base = smb + (kb % STG) * STAGE;
        const uint32_t aB = base, bB = base + TA;
#pragma unroll
        for (int ks = 0; ks < 2; ks++) {
            const uint32_t aoff = (uint32_t)(wm * 64 + (lane & 15)) * 80
                                + ks * 32 + (lane >> 4) * 16;
            uint32_t Af[MI][4];
#pragma unroll
            for (int mi = 0; mi < MI; mi++)
                ldsm4(Af[mi][0], Af[mi][1], Af[mi][2], Af[mi][3], aB + aoff + mi * 16 * 80);
            uint32_t Bf[8];
            if (BT) {
                const uint32_t kk = (uint32_t)(ks * 16 + (lane & 15));
                const uint32_t bo = bB + kk * 272 + wn * 64 + ((lane >> 4) << 4);
                ldsm4t(Bf[0], Bf[1], Bf[2], Bf[3], bo);
                ldsm4t(Bf[4], Bf[5], Bf[6], Bf[7], bo + 32);
            } else {
                const uint32_t boff = (uint32_t)(wn * 32 + ((lane >> 4) << 3) + (lane & 7)) * 80
                                    + ks * 32 + ((lane >> 3) & 1) * 16;
                ldsm4(Bf[0], Bf[1], Bf[2], Bf[3], bB + boff);
                ldsm4(Bf[4], Bf[5], Bf[6], Bf[7], bB + boff + 16 * 80);
            }
#pragma unroll
            for (int mi = 0; mi < MI; mi++)
#pragma unroll
                for (int ni = 0; ni < 4; ni++)
                    mma_f16(acc[mi][ni], Af[mi], &Bf[2 * ni]);
        }
    }

    __syncthreads();
    float* Cp = reinterpret_cast<float*>(sm);

    if (EPI == 1) {
        // row-major staging [128][132]
#pragma unroll
        for (int mi = 0; mi < MI; mi++)
#pragma unroll
            for (int ni = 0; ni < 4; ni++)
#pragma unroll
                for (int r = 0; r < 4; r++) {
                    const int ml = wm * 64 + mi * 16 + (lane >> 2) + ((r >> 1) ? 8 : 0);
                    const int nl = wn * 32 + ni * 8 + 2 * (lane & 3) + (r & 1);
                    Cp[ml * 132 + nl] = acc[mi][ni][r];
                }
        __syncthreads();
#pragma unroll
        for (int i = tid; i < 128 * 32; i += 256) {
            const int ml = i >> 5, j4 = (i & 31) << 2;
            float4 v = *reinterpret_cast<float4*>(&Cp[ml * 132 + j4]);
            const size_t o = (size_t)(m0 + ml) * NU + n0 + j4;
            *reinterpret_cast<uint2*>(&g_sU[o]) = make_uint2(pkh2(v.x, v.y), pkh2(v.z, v.w));
        }
    } else {
        // transposed staging Cp_T[nl][ml], stride 140 (conflict-free STS & float4 LDS)
#pragma unroll
        for (int mi = 0; mi < MI; mi++)
#pragma unroll
            for (int ni = 0; ni < 4; ni++)
#pragma unroll
                for (int r = 0; r < 4; r++) {
                    const int ml = wm * 64 + mi * 16 + (lane >> 2) + ((r >> 1) ? 8 : 0);
                    const int nl = wn * 32 + ni * 8 + 2 * (lane & 3) + (r & 1);
                    Cp[nl * 140 + ml] = acc[mi][ni][r];
                }
        __syncthreads();

        const int b = m0 >> 12;
        const int s_base = (m0 >> 4) & 255;
        const float* eweB0 = g_prE[0] + (b << 12) + (n0 << 4);
        const float* eweB1 = g_prE[1] + (b << 12) + (n0 << 4);
        // 16384 outputs = 4096 float4; idx -> e = idx>>5, sl = (idx&31)>>2, cq = (idx&3)*4
#pragma unroll
        for (int k = 0; k < 16; k++) {
            const int idx = tid + k * 256;
            const int e = idx >> 5;
            const int sl_ = (idx & 31) >> 2;
            const int cq = (idx & 3) << 2;
            const int mrow = sl_ * 16 + cq;
            const int s = s_base + sl_;

            float4 v = *reinterpret_cast<float4*>(&Cp[e * 140 + mrow]);
            float4 ew0 = *reinterpret_cast<const float4*>(&eweB0[e * 16 + cq]);
            float4 ew1 = *reinterpret_cast<const float4*>(&eweB1[e * 16 + cq]);
            float4 wv  = *reinterpret_cast<const float4*>(&g_whWw[(((s << 8) + n0 + e) << 4) + cq]);
            float4 sw0 = *reinterpret_cast<const float4*>(&g_prS[0][m0 + mrow]);
            float4 sw1 = *reinterpret_cast<const float4*>(&g_prS[1][m0 + mrow]);
            float4 lb  = *reinterpret_cast<const float4*>(&p0[cq]);
            v.x += ew0.x + ew1.x + wv.x + sw0.x + sw1.x + lb.x;
            v.y += ew0.y + ew1.y + wv.y + sw0.y + sw1.y + lb.y;
            v.z += ew0.z + ew1.z + wv.z + sw0.z + sw1.z + lb.z;
            v.w += ew0.w + ew1.w + wv.w + sw0.w + sw1.w + lb.w;
            float* obase = outp + (((size_t)(b * 256 + s)) * 256 + n0 + e) * 16;
            *reinterpret_cast<float4*>(&obase[cq]) = v;
        }
    }
}

// ---------------------------------------------------------------------------
// gemm0_fat: [0,128) s/e GEMM + fused proj ; [128,192) U convert ; [192,448) wh_proj
// ---------------------------------------------------------------------------
__global__ void __launch_bounds__(256, 3)
gemm0_fat(const float* __restrict__ sb, const float* __restrict__ eb,
          const float* __restrict__ linW, const float* __restrict__ U,
          const float* __restrict__ wh)
{
    extern __shared__ char sm[];
    const int bx = blockIdx.x;
    const int tid = threadIdx.x;

    if (bx >= 192) {                         // ---------------- wh_proj
        float* tileS = reinterpret_cast<float*>(sm);
        float* WwS   = tileS + 64 * WDd;
        {
            float4 a = reinterpret_cast<const float4*>(linW + 2 * Tt * Cc)[tid];
            *reinterpret_cast<float4*>(&WwS[tid * 4]) = a;
        }
        const int c = tid & 15, pl0 = (tid >> 4) * 4;
        for (int it = 0; it < 4; it++) {
            const int p0 = (bx - 192) * 256 + it * 64;
            __syncthreads();
            const float4* src = reinterpret_cast<const float4*>(wh + (size_t)p0 * WDd);
#pragma unroll
            for (int l = 0; l < 4; l++) {
                float4 b = src[tid + l * 256];
                *reinterpret_cast<float4*>(&tileS[(tid + l * 256) * 4]) = b;
            }
            __syncthreads();
#pragma unroll
            for (int r = 0; r < 4; r++) {
                const int pl = pl0 + r;
                float acc = 0.f;
#pragma unroll
                for (int w = 0; w < WDd; w++)
                    acc += tileS[pl * WDd + w] * WwS[w * Cc + c];
                g_whWw[(p0 + pl) * Cc + c] = acc;
            }
        }
        return;
    }
    if (bx >= 128) {                         // ---------------- U convert
        const int base = (bx - 128) * 256 + tid;
#pragma unroll
        for (int it = 0; it < 16; it++) {
            const int j = base + it * 16384;
            float4 v = reinterpret_cast<const float4*>(U)[j];
            *reinterpret_cast<uint2*>(&g_U16[(size_t)j * 4]) =
                make_uint2(pkh2(v.x, v.y), pkh2(v.z, v.w));
        }
        return;
    }

    // ---------------- s/e projection GEMM, MT=32, BT
    constexpr int MT = 32;
    constexpr int TA = MT * 80;
    constexpr int TB = 32 * 272;
    constexpr int STAGE = TA + TB;

    const uint32_t smb = smem_u32(sm);
    const int lane = tid & 31, w = tid >> 5;
    const int wm = w >> 2, wn = w & 3;
    const int m0 = (bx >> 2) * MT, n0 = (bx & 3) * 128;
    const __half* A  = g_x + (size_t)m0 * HF;
    const __half* Bg = (n0 < 256) ? g_sW16 : g_eW16;
    const int bn0 = n0 & 255;
    constexpr int ldn = 256;

    float acc[1][4][4] = {};
    const int nk = HF / 32;   // 25

    auto load_stage = [&](int st, int kb) {
        const uint32_t sbm = smb + st * STAGE;
        const int kc = kb * 32;
#pragma unroll
        for (int i = tid; i < MT * 4; i += 256) {
            const int row = i >> 2, ch = i & 3;
            cpa16(sbm + row * 80 + ch * 16, A + (size_t)row * HF + kc + ch * 8);
        }
#pragma unroll
        for (int i = tid; i < 512; i += 256) {
            const int row = i >> 4, ch = i & 15;
            cpa16(sbm + TA + row * 272 + ch * 16,
                  Bg + (size_t)(kc + row) * ldn + bn0 + ch * 8);
        }
    };

#pragma unroll
    for (int s = 0; s < STG - 1; s++) {
        if (s < nk) load_stage(s, s);
        CP_COMMIT();
    }
    for (int kb = 0; kb < nk; kb++) {
        CP_WAIT(STG - 2);
        __syncthreads();
        const int nx = kb + STG - 1;
        if (nx < nk) load_stage(nx % STG, nx);
        CP_COMMIT();

        const uint32_t base = smb + (kb % STG) * STAGE;
        const uint32_t aB = base, bB = base + TA;
#pragma unroll
        for (int ks = 0; ks < 2; ks++) {
            const uint32_t aoff = (uint32_t)(wm * 16 + (lane & 15)) * 80
                                + ks * 32 + (lane >> 4) * 16;
            uint32_t Af[4];
            ldsm4(Af[0], Af[1], Af[2], Af[3], aB + aoff);
            uint32_t Bf[8];
            const uint32_t kk = (uint32_t)(ks * 16 + (lane & 15));
            const uint32_t bo = bB + kk * 272 + wn * 64 + ((lane >> 4) << 4);
            ldsm4t(Bf[0], Bf[1], Bf[2], Bf[3], bo);
            ldsm4t(Bf[4], Bf[5], Bf[6], Bf[7], bo + 32);
#pragma unroll
            for (int ni = 0; ni < 4; ni++)
                mma_f16(acc[0][ni], Af, &Bf[2 * ni]);
        }
    }

    __syncthreads();
    float* Cp = reinterpret_cast<float*>(sm);   // [32][132]
#pragma unroll
    for (int ni = 0; ni < 4; ni++)
#pragma unroll
        for (int r = 0; r < 4; r++) {
            const int ml = wm * 16 + (lane >> 2) + ((r >> 1) ? 8 : 0);
            const int nl = wn * 32 + ni * 8 + 2 * (lane & 3) + (r & 1);
            Cp[ml * 132 + nl] = acc[0][ni][r];
        }
    __syncthreads();

    const float* bias = (n0 < 256) ? sb : eb;
    __half* dst = (n0 < 256) ? g_s16 : g_e16;
    const int nc0 = n0 & 255;
#pragma unroll
    for (int i = tid; i < 32 * 32; i += 256) {
        const int ml = i >> 5, j4 = (i & 31) << 2;
        float4 v = *reinterpret_cast<float4*>(&Cp[ml * 132 + j4]);
        const int nc = nc0 + j4;
        v.x += bias[nc]; v.y += bias[nc + 1]; v.z += bias[nc + 2]; v.w += bias[nc + 3];
        *reinterpret_cast<float4*>(&Cp[ml * 132 + j4]) = v;
        const size_t o = (size_t)(m0 + ml) * Tt + nc;
        *reinterpret_cast<uint2*>(&dst[o]) = make_uint2(pkh2(v.x, v.y), pkh2(v.z, v.w));
    }
    float* Wp = Cp + 32 * 132;
#pragma unroll
    for (int i = tid; i < 512; i += 256)
        *reinterpret_cast<float4*>(&Wp[i * 4]) =
            reinterpret_cast<const float4*>(linW)[n0 * 4 + i];
    __syncthreads();
    float* dpr = (n0 < 256) ? g_prS[(n0 >> 7) & 1] : g_prE[(n0 >> 7) & 1];
    const int c = lane & 15, th = lane >> 4;
    float ap[4] = {};
#pragma unroll 8
    for (int j = 0; j < 64; j++) {
        const int t = th * 64 + j;
        const float wv = Wp[t * Cc + c];
#pragma unroll
        for (int r = 0; r < 4; r++)
            ap[r] += Cp[(w * 4 + r) * 132 + t] * wv;
    }
#pragma unroll
    for (int r = 0; r < 4; r++)
        ap[r] += __shfl_xor_sync(0xffffffff, ap[r], 16);
    if (lane < 16) {
#pragma unroll
        for (int r = 0; r < 4; r++)
            dpr[(m0 + w * 4 + r) * Cc + c] = ap[r];
    }
}

// ---------------------------------------------------------------------------
__global__ void prep_xw(const float* __restrict__ fh, const float* __restrict__ fv,
                        const float* __restrict__ sW, const float* __restrict__ eW)
{
    const int i = blockIdx.x * 256 + threadIdx.x;
    float4 v;
    __half* dst;
    size_t o;
    if (i < 51200) {
        v = reinterpret_cast<const float4*>(sW)[i];
        dst = g_sW16; o = (size_t)i * 4;
    } else if (i < 102400) {
        const int j = i - 51200;
        v = reinterpret_cast<const float4*>(eW)[j];
        dst = g_eW16; o = (size_t)j * 4;
    } else {
        const int j = i - 102400;
        const int row = j / 200, c4 = j % 200;
        if (c4 < 192) v = reinterpret_cast<const float4*>(fh)[row * 192 + c4];
        else          v = reinterpret_cast<const float4*>(fv)[row * 8 + (c4 - 192)];
        dst = g_x; o = (size_t)row * HF + c4 * 4;
    }
    *reinterpret_cast<uint2*>(&dst[o]) = make_uint2(pkh2(v.x, v.y), pkh2(v.z, v.w));
}

// ------------------------------- launch
extern "C" void kernel_launch(void* const* d_in, const int* in_sizes, int n_in,
                              void* d_out, int out_size)
{
    const float* fh   = (const float*)d_in[0];
    const float* fv   = (const float*)d_in[1];
    const float* sW   = (const float*)d_in[2];
    const float* sb   = (const float*)d_in[3];
    const float* eW   = (const float*)d_in[4];
    const float* eb   = (const float*)d_in[5];
    const float* U    = (const float*)d_in[6];
    const float* wh   = (const float*)d_in[7];
    const float* linW = (const float*)d_in[8];
    const float* linb = (const float*)d_in[9];
    float* out = (float*)d_out;

    constexpr int SMEM_G0 = STG * 11264;             // 45056
    constexpr int SMEM_G1 = STG * (128*80 + 32*272); // 75776 >= 67584 staging
    constexpr int SMEM_G2 = STG * (128*80 + 128*80); // 81920 >= 128*140*4=71680 staging

    cudaFuncSetAttribute(gemm0_fat,          cudaFuncAttributeMaxDynamicSharedMemorySize, SMEM_G0);
    cudaFuncSetAttribute(mma_gemm<1, true>,  cudaFuncAttributeMaxDynamicSharedMemorySize, SMEM_G1);
    cudaFuncSetAttribute(mma_gemm<2, false>, cudaFuncAttributeMaxDynamicSharedMemorySize, SMEM_G2);

    prep_xw<<<1200, 256>>>(fh, fv, sW, eW);
    gemm0_fat<<<448, 256, SMEM_G0>>>(sb, eb, linW, U, wh);
    mma_gemm<1, true><<<dim3(32, 8), 256, SMEM_G1>>>(nullptr, nullptr, Tt);   // sU
    mma_gemm<2, false><<<dim3(2, 32, 4), 256, SMEM_G2>>>(linb, out, Tt);      // pre
}

// round 15
// speedup vs baseline: 1.0330x; 1.0330x over previous
#include <cuda_runtime.h>
#include <cuda_fp16.h>
#include <cstdint>

#define Hh 768
#define Ff 32
#define Tt 256
#define HF 800
#define BSr 1024
#define NU 4096
#define Cc 16
#define WDd 64
#define Ss 256

// ------------------------------- scratch (device globals)
__device__ __align__(256) __half g_x   [BSr * HF];
__device__ __align__(256) __half g_sW16[HF * Tt];
__device__ __align__(256) __half g_eW16[HF * Tt];
__device__ __align__(256) __half g_U16 [Tt * NU];
__device__ __align__(256) __half g_s16 [BSr * Tt];
__device__ __align__(256) __half g_e16 [BSr * Tt];
__device__ __align__(256) __half g_sU  [BSr * NU];
__device__ float g_prS[2][BSr * Cc];
__device__ float g_prE[2][BSr * Cc];
__device__ __align__(256) __half g_whWw16[Ss * Ss * Cc];   // fp16: halves L2 stream

// ------------------------------- PTX helpers
__device__ __forceinline__ uint32_t smem_u32(const void* p) {
    uint32_t a;
    asm("{ .reg .u64 t; cvta.to.shared.u64 t, %1; cvt.u32.u64 %0, t; }" : "=r"(a) : "l"(p));
    return a;
}
__device__ __forceinline__ void cpa16(uint32_t dst, const void* src) {
    asm volatile("cp.async.cg.shared.global [%0], [%1], 16;" :: "r"(dst), "l"(src));
}
#define CP_COMMIT() asm volatile("cp.async.commit_group;" ::: "memory")
#define CP_WAIT(n)  asm volatile("cp.async.wait_group %0;" :: "n"(n) : "memory")

__device__ __forceinline__ void ldsm4(uint32_t& r0, uint32_t& r1, uint32_t& r2, uint32_t& r3, uint32_t a) {
    asm volatile("ldmatrix.sync.aligned.m8n8.x4.shared.b16 {%0,%1,%2,%3}, [%4];"
                 : "=r"(r0), "=r"(r1), "=r"(r2), "=r"(r3) : "r"(a));
}
__device__ __forceinline__ void ldsm4t(uint32_t& r0, uint32_t& r1, uint32_t& r2, uint32_t& r3, uint32_t a) {
    asm volatile("ldmatrix.sync.aligned.m8n8.x4.trans.shared.b16 {%0,%1,%2,%3}, [%4];"
                 : "=r"(r0), "=r"(r1), "=r"(r2), "=r"(r3) : "r"(a));
}
__device__ __forceinline__ void mma_f16(float* c, const uint32_t* a, const uint32_t* b) {
    asm volatile("mma.sync.aligned.m16n8k16.row.col.f32.f16.f16.f32 "
                 "{%0,%1,%2,%3},{%4,%5,%6,%7},{%8,%9},{%0,%1,%2,%3};"
                 : "+f"(c[0]), "+f"(c[1]), "+f"(c[2]), "+f"(c[3])
                 : "r"(a[0]), "r"(a[1]), "r"(a[2]), "r"(a[3]), "r"(b[0]), "r"(b[1]));
}
__device__ __forceinline__ uint32_t pkh2(float a, float b) {
    __half2 t = __floats2half2_rn(a, b);
    return *reinterpret_cast<uint32_t*>(&t);
}
__device__ __forceinline__ void stcs4(float* p, float4 v) {
    asm volatile("st.global.cs.v4.f32 [%0], {%1,%2,%3,%4};"
                 :: "l"(p), "f"(v.x), "f"(v.y), "f"(v.z), "f"(v.w) : "memory");
}

constexpr int STG = 4;

// ---------------------------------------------------------------------------
// Big GEMMs at the legacy-mma issue ceiling: MT=128, occ 2.
// EPI: 1 = sU, 2 = pre (+ fused FFN terms; row-major staging, R13-proven)
// ---------------------------------------------------------------------------
template<int EPI, bool BT>
__global__ void __launch_bounds__(256, 2)
mma_gemm(const float* __restrict__ p0, float* __restrict__ outp, int K)
{
    constexpr int MT = 128;
    constexpr int TA = MT * 80;
    constexpr int TB = BT ? 32 * 272 : 128 * 80;
    constexpr int STAGE = TA + TB;
    constexpr int MI = 4;

    extern __shared__ char sm[];
    const uint32_t smb = smem_u32(sm);
    const int tid = threadIdx.x, lane = tid & 31, w = tid >> 5;
    const int wm = w >> 2, wn = w & 3;

    int m0, n0;
    const __half *A, *Bg;
    int lda, ldn, bn0 = 0;
    if (EPI == 1) {
        m0 = blockIdx.y * MT; n0 = blockIdx.x * 128; lda = Tt;
        A = g_s16 + (size_t)m0 * Tt;
        Bg = g_U16; bn0 = n0; ldn = NU;
    } else {
        const int b = blockIdx.z;
        m0 = b * 4096 + blockIdx.y * MT; n0 = blockIdx.x * 128; lda = Tt;
        A = g_sU + (size_t)m0 * Tt;
        Bg = g_e16 + (size_t)b * Ss * Tt + (size_t)n0 * Tt;
        ldn = Tt;
    }

    float acc[MI][4][4] = {};
    const int nk = K / 32;

    auto load_stage = [&](int st, int kb) {
        const uint32_t sb = smb + st * STAGE;
        const int kc = kb * 32;
#pragma unroll
        for (int i = tid; i < MT * 4; i += 256) {
            const int row = i >> 2, ch = i & 3;
            cpa16(sb + row * 80 + ch * 16, A + (size_t)row * lda + kc + ch * 8);
        }
        if (BT) {
#pragma unroll
            for (int i = tid; i < 512; i += 256) {
                const int row = i >> 4, ch = i & 15;
                cpa16(sb + TA + row * 272 + ch * 16,
                      Bg + (size_t)(kc + row) * ldn + bn0 + ch * 8);
            }
        } else {
#pragma unroll
            for (int i = tid; i < 512; i += 256) {
                const int row = i >> 2, ch = i & 3;
                cpa16(sb + TA + row * 80 + ch * 16,
                      Bg + (size_t)row * ldn + kc + ch * 8);
            }
        }
    };

#pragma unroll
    for (int s = 0; s < STG - 1; s++) {
        if (s < nk) load_stage(s, s);
        CP_COMMIT();
    }

    for (int kb = 0; kb < nk; kb++) {
        CP_WAIT(STG - 2);
        __syncthreads();
        const int nx = kb + STG - 1;
        if (nx < nk) load_stage(nx % STG, nx);
        CP_COMMIT();

        const uint32_t base = smb + (kb % STG) * STAGE;
        const uint32_t aB = base, bB = base + TA;
#pragma unroll
        for (int ks = 0; ks < 2; ks++) {
            const uint32_t aoff = (uint32_t)(wm * 64 + (lane & 15)) * 80
                                + ks * 32 + (lane >> 4) * 16;
            uint32_t Af[MI][4];
#pragma unroll
            for (int mi = 0; mi < MI; mi++)
                ldsm4(Af[mi][0], Af[mi][1], Af[mi][2], Af[mi][3], aB + aoff + mi * 16 * 80);
            uint32_t Bf[8];
            if (BT) {
                const uint32_t kk = (uint32_t)(ks * 16 + (lane & 15));
                const uint32_t bo = bB + kk * 272 + wn * 64 + ((lane >> 4) << 4);
                ldsm4t(Bf[0], Bf[1], Bf[2], Bf[3], bo);
                ldsm4t(Bf[4], Bf[5], Bf[6], Bf[7], bo + 32);
            } else {
                const uint32_t boff = (uint32_t)(wn * 32 + ((lane >> 4) << 3) + (lane & 7)) * 80
                                    + ks * 32 + ((lane >> 3) & 1) * 16;
                ldsm4(Bf[0], Bf[1], Bf[2], Bf[3], bB + boff);
                ldsm4(Bf[4], Bf[5], Bf[6], Bf[7], bB + boff + 16 * 80);
            }
#pragma unroll
            for (int mi = 0; mi < MI; mi++)
#pragma unroll
                for (int ni = 0; ni < 4; ni++)
                    mma_f16(acc[mi][ni], Af[mi], &Bf[2 * ni]);
        }
    }

    __syncthreads();
    float* Cp = reinterpret_cast<float*>(sm);   // [128][132] row-major
#pragma unroll
    for (int mi = 0; mi < MI; mi++)
#pragma unroll
        for (int ni = 0; ni < 4; ni++)
#pragma unroll
            for (int r = 0; r < 4; r++) {
                const int ml = wm * 64 + mi * 16 + (lane >> 2) + ((r >> 1) ? 8 : 0);
                const int nl = wn * 32 + ni * 8 + 2 * (lane & 3) + (r & 1);
                Cp[ml * 132 + nl] = acc[mi][ni][r];
            }
    __syncthreads();

    if (EPI == 1) {
#pragma unroll
        for (int i = tid; i < 128 * 32; i += 256) {
            const int ml = i >> 5, j4 = (i & 31) << 2;
            float4 v = *reinterpret_cast<float4*>(&Cp[ml * 132 + j4]);
            const size_t o = (size_t)(m0 + ml) * NU + n0 + j4;
            *reinterpret_cast<uint2*>(&g_sU[o]) = make_uint2(pkh2(v.x, v.y), pkh2(v.z, v.w));
        }
    } else {
        const int b = m0 >> 12;
        const int s_base = (m0 >> 4) & 255;
#pragma unroll
        for (int sl_ = 0; sl_ < 8; sl_++) {
            const int s = s_base + sl_;
            float* obase = outp + (((size_t)(b * 256 + s)) * 256 + n0) * 16;
            const int eoff = (b << 12) + (n0 << 4);
            const __half* whB = g_whWw16 + (((s << 8) + n0) << 4);
            const int swoff = m0 + sl_ * 16;
#pragma unroll
            for (int i = tid; i < 512; i += 256) {
                const int e = i >> 2, cq = (i & 3) << 2;
                const int mrow = sl_ * 16 + cq;
                float4 v;
                v.x = Cp[(mrow + 0) * 132 + e];
                v.y = Cp[(mrow + 1) * 132 + e];
                v.z = Cp[(mrow + 2) * 132 + e];
                v.w = Cp[(mrow + 3) * 132 + e];
                float4 ew0 = *reinterpret_cast<const float4*>(&g_prE[0][eoff + e * 16 + cq]);
                float4 ew1 = *reinterpret_cast<const float4*>(&g_prE[1][eoff + e * 16 + cq]);
                const __half2* wh2 = reinterpret_cast<const __half2*>(&whB[e * 16 + cq]);
                float2 wva = __half22float2(wh2[0]);
                float2 wvb = __half22float2(wh2[1]);
                float4 sw0 = *reinterpret_cast<const float4*>(&g_prS[0][swoff + cq]);
                float4 sw1 = *reinterpret_cast<const float4*>(&g_prS[1][swoff + cq]);
                float4 lb  = *reinterpret_cast<const float4*>(&p0[cq]);
                v.x += ew0.x + ew1.x + wva.x + sw0.x + sw1.x + lb.x;
                v.y += ew0.y + ew1.y + wva.y + sw0.y + sw1.y + lb.y;
                v.z += ew0.z + ew1.z + wvb.x + sw0.z + sw1.z + lb.z;
                v.w += ew0.w + ew1.w + wvb.y + sw0.w + sw1.w + lb.w;
                stcs4(&obase[e * 16 + cq], v);
            }
        }
    }
}

// ---------------------------------------------------------------------------
// gemm0_fat: [0,128) s/e GEMM + fused proj ; [128,192) U convert ; [192,448) wh_proj
// ---------------------------------------------------------------------------
__global__ void __launch_bounds__(256, 3)
gemm0_fat(const float* __restrict__ sb, const float* __restrict__ eb,
          const float* __restrict__ linW, const float* __restrict__ U,
          const float* __restrict__ wh)
{
    extern __shared__ char sm[];
    const int bx = blockIdx.x;
    const int tid = threadIdx.x;

    if (bx >= 192) {                         // ---------------- wh_proj (fp16 out)
        float* tileS = reinterpret_cast<float*>(sm);
        float* WwS   = tileS + 64 * WDd;
        {
            float4 a = reinterpret_cast<const float4*>(linW + 2 * Tt * Cc)[tid];
            *reinterpret_cast<float4*>(&WwS[tid * 4]) = a;
        }
        const int c = tid & 15, pl0 = (tid >> 4) * 4;
        for (int it = 0; it < 4; it++) {
            const int p0 = (bx - 192) * 256 + it * 64;
            __syncthreads();
            const float4* src = reinterpret_cast<const float4*>(wh + (size_t)p0 * WDd);
#pragma unroll
            for (int l = 0; l < 4; l++) {
                float4 b = src[tid + l * 256];
                *reinterpret_cast<float4*>(&tileS[(tid + l * 256) * 4]) = b;
            }
            __syncthreads();
#pragma unroll
            for (int r = 0; r < 4; r++) {
                const int pl = pl0 + r;
                float acc = 0.f;
#pragma unroll
                for (int w = 0; w < WDd; w++)
                    acc += tileS[pl * WDd + w] * WwS[w * Cc + c];
                g_whWw16[(p0 + pl) * Cc + c] = __float2half(acc);
            }
        }
        return;
    }
    if (bx >= 128) {                         // ---------------- U convert
        const int base = (bx - 128) * 256 + tid;
#pragma unroll
        for (int it = 0; it < 16; it++) {
            const int j = base + it * 16384;
            float4 v = reinterpret_cast<const float4*>(U)[j];
            *reinterpret_cast<uint2*>(&g_U16[(size_t)j * 4]) =
                make_uint2(pkh2(v.x, v.y), pkh2(v.z, v.w));
        }
        return;
    }

    // ---------------- s/e projection GEMM, MT=32, BT
    constexpr int MT = 32;
    constexpr int TA = MT * 80;
    constexpr int TB = 32 * 272;
    constexpr int STAGE = TA + TB;

    const uint32_t smb = smem_u32(sm);
    const int lane = tid & 31, w = tid >> 5;
    const int wm = w >> 2, wn = w & 3;
    const int m0 = (bx >> 2) * MT, n0 = (bx & 3) * 128;
    const __half* A  = g_x + (size_t)m0 * HF;
    const __half* Bg = (n0 < 256) ? g_sW16 : g_eW16;
    const int bn0 = n0 & 255;
    constexpr int ldn = 256;

    float acc[1][4][4] = {};
    const int nk = HF / 32;   // 25

    auto load_stage = [&](int st, int kb) {
        const uint32_t sbm = smb + st * STAGE;
        const int kc = kb * 32;
#pragma unroll
        for (int i = tid; i < MT * 4; i += 256) {
            const int row = i >> 2, ch = i & 3;
            cpa16(sbm + row * 80 + ch * 16, A + (size_t)row * HF + kc + ch * 8);
        }
#pragma unroll
        for (int i = tid; i < 512; i += 256) {
            const int row = i >> 4, ch = i & 15;
            cpa16(sbm + TA + row * 272 + ch * 16,
                  Bg + (size_t)(kc + row) * ldn + bn0 + ch * 8);
        }
    };

#pragma unroll
    for (int s = 0; s < STG - 1; s++) {
        if (s < nk) load_stage(s, s);
        CP_COMMIT();
    }
    for (int kb = 0; kb < nk; kb++) {
        CP_WAIT(STG - 2);
        __syncthreads();
        const int nx = kb + STG - 1;
        if (nx < nk) load_stage(nx % STG, nx);
        CP_COMMIT();

        const uint32_t base = smb + (kb % STG) * STAGE;
        const uint32_t aB = base, bB = base + TA;
#pragma unroll
        for (int ks = 0; ks < 2; ks++) {
            const uint32_t aoff = (uint32_t)(wm * 16 + (lane & 15)) * 80
                                + ks * 32 + (lane >> 4) * 16;
            uint32_t Af[4];
            ldsm4(Af[0], Af[1], Af[2], Af[3], aB + aoff);
            uint32_t Bf[8];
            const uint32_t kk = (uint32_t)(ks * 16 + (lane & 15));
            const uint32_t bo = bB + kk * 272 + wn * 64 + ((lane >> 4) << 4);
            ldsm4t(Bf[0], Bf[1], Bf[2], Bf[3], bo);
            ldsm4t(Bf[4], Bf[5], Bf[6], Bf[7], bo + 32);
#pragma unroll
            for (int ni = 0; ni < 4; ni++)
                mma_f16(acc[0][ni], Af, &Bf[2 * ni]);
        }
    }

    __syncthreads();
    float* Cp = reinterpret_cast<float*>(sm);   // [32][132]
#pragma unroll
    for (int ni = 0; ni < 4; ni++)
#pragma unroll
        for (int r = 0; r < 4; r++) {
            const int ml = wm * 16 + (lane >> 2) + ((r >> 1) ? 8 : 0);
            const int nl = wn * 32 + ni * 8 + 2 * (lane & 3) + (r & 1);
            Cp[ml * 132 + nl] = acc[0][ni][r];
        }
    __syncthreads();

    const float* bias = (n0 < 256) ? sb : eb;
    __half* dst = (n0 < 256) ? g_s16 : g_e16;
    const int nc0 = n0 & 255;
#pragma unroll
    for (int i = tid; i < 32 * 32; i += 256) {
        const int ml = i >> 5, j4 = (i & 31) << 2;
        float4 v = *reinterpret_cast<float4*>(&Cp[ml * 132 + j4]);
        const int nc = nc0 + j4;
        v.x += bias[nc]; v.y += bias[nc + 1]; v.z += bias[nc + 2]; v.w += bias[nc + 3];
        *reinterpret_cast<float4*>(&Cp[ml * 132 + j4]) = v;
        const size_t o = (size_t)(m0 + ml) * Tt + nc;
        *reinterpret_cast<uint2*>(&dst[o]) = make_uint2(pkh2(v.x, v.y), pkh2(v.z, v.w));
    }
    float* Wp = Cp + 32 * 132;
#pragma unroll
    for (int i = tid; i < 512; i += 256)
        *reinterpret_cast<float4*>(&Wp[i * 4]) =
            reinterpret_cast<const float4*>(linW)[n0 * 4 + i];
    __syncthreads();
    float* dpr = (n0 < 256) ? g_prS[(n0 >> 7) & 1] : g_prE[(n0 >> 7) & 1];
    const int c = lane & 15, th = lane >> 4;
    float ap[4] = {};
#pragma unroll 8
    for (int j = 0; j < 64; j++) {
        const int t = th * 64 + j;
        const float wv = Wp[t * Cc + c];
#pragma unroll
        for (int r = 0; r < 4; r++)
            ap[r] += Cp[(w * 4 + r) * 132 + t] * wv;
    }
#pragma unroll
    for (int r = 0; r < 4; r++)
        ap[r] += __shfl_xor_sync(0xffffffff, ap[r], 16);
    if (lane < 16) {
#pragma unroll
        for (int r = 0; r < 4; r++)
            dpr[(m0 + w * 4 + r) * Cc + c] = ap[r];
    }
}

// ---------------------------------------------------------------------------
__global__ void prep_xw(const float* __restrict__ fh, const float* __restrict__ fv,
                        const float* __restrict__ sW, const float* __restrict__ eW)
{
    const int i = blockIdx.x * 256 + threadIdx.x;
    float4 v;
    __half* dst;
    size_t o;
    if (i < 51200) {
        v = reinterpret_cast<const float4*>(sW)[i];
        dst = g_sW16; o = (size_t)i * 4;
    } else if (i < 102400) {
        const int j = i - 51200;
        v = reinterpret_cast<const float4*>(eW)[j];
        dst = g_eW16; o = (size_t)j * 4;
    } else {
        const int j = i - 102400;
        const int row = j / 200, c4 = j % 200;
        if (c4 < 192) v = reinterpret_cast<const float4*>(fh)[row * 192 + c4];
        else          v = reinterpret_cast<const float4*>(fv)[row * 8 + (c4 - 192)];
        dst = g_x; o = (size_t)row * HF + c4 * 4;
    }
    *reinterpret_cast<uint2*>(&dst[o]) = make_uint2(pkh2(v.x, v.y), pkh2(v.z, v.w));
}

// ------------------------------- launch
extern "C" void kernel_launch(void* const* d_in, const int* in_sizes, int n_in,
                              void* d_out, int out_size)
{
    const float* fh   = (const float*)d_in[0];
    const float* fv   = (const float*)d_in[1];
    const float* sW   = (const float*)d_in[2];
    const float* sb   = (const float*)d_in[3];
    const float* eW   = (const float*)d_in[4];
    const float* eb   = (const float*)d_in[5];
    const float* U    = (const float*)d_in[6];
    const float* wh   = (const float*)d_in[7];
    const float* linW = (const float*)d_in[8];
    const float* linb = (const float*)d_in[9];
    float* out = (float*)d_out;

    constexpr int SMEM_G0 = STG * 11264;             // 45056
    constexpr int SMEM_G1 = STG * (128*80 + 32*272); // 75776 >= 67584 staging
    constexpr int SMEM_G2 = STG * (128*80 + 128*80); // 81920 >= 67584 staging

    cudaFuncSetAttribute(gemm0_fat,          cudaFuncAttributeMaxDynamicSharedMemorySize, SMEM_G0);
    cudaFuncSetAttribute(mma_gemm<1, true>,  cudaFuncAttributeMaxDynamicSharedMemorySize, SMEM_G1);
    cudaFuncSetAttribute(mma_gemm<2, false>, cudaFuncAttributeMaxDynamicSharedMemorySize, SMEM_G2);

    prep_xw<<<1200, 256>>>(fh, fv, sW, eW);
    gemm0_fat<<<448, 256, SMEM_G0>>>(sb, eb, linW, U, wh);
    mma_gemm<1, true><<<dim3(32, 8), 256, SMEM_G1>>>(nullptr, nullptr, Tt);   // sU
    mma_gemm<2, false><<<dim3(2, 32, 4), 256, SMEM_G2>>>(linb, out, Tt);      // pre
}

// round 16
// speedup vs baseline: 1.1017x; 1.0665x over previous
#include <cuda_runtime.h>
#include <cuda_fp16.h>
#include <cstdint>

#define Hh 768
#define Ff 32
#define Tt 256
#define HF 800
#define BSr 1024
#define NU 4096
#define Cc 16
#define WDd 64
#define Ss 256

// ------------------------------- scratch (device globals)
__device__ __align__(256) __half g_x   [BSr * HF];
__device__ __align__(256) __half g_sW16[HF * Tt];
__device__ __align__(256) __half g_eW16[HF * Tt];
__device__ __align__(256) __half g_U16 [Tt * NU];
__device__ __align__(256) __half g_s16 [BSr * Tt];
__device__ __align__(256) __half g_e16 [BSr * Tt];
__device__ __align__(256) __half g_sU  [BSr * NU];
__device__ __align__(256) __half g_prS16[2][BSr * Cc];
__device__ __align__(256) __half g_prE16[2][BSr * Cc];
__device__ __align__(256) __half g_whWw16[Ss * Ss * Cc];

// ------------------------------- PTX helpers
__device__ __forceinline__ uint32_t smem_u32(const void* p) {
    uint32_t a;
    asm("{ .reg .u64 t; cvta.to.shared.u64 t, %1; cvt.u32.u64 %0, t; }" : "=r"(a) : "l"(p));
    return a;
}
__device__ __forceinline__ void cpa16(uint32_t dst, const void* src) {
    asm volatile("cp.async.cg.shared.global [%0], [%1], 16;" :: "r"(dst), "l"(src));
}
#define CP_COMMIT() asm volatile("cp.async.commit_group;" ::: "memory")
#define CP_WAIT(n)  asm volatile("cp.async.wait_group %0;" :: "n"(n) : "memory")

__device__ __forceinline__ void ldsm4(uint32_t& r0, uint32_t& r1, uint32_t& r2, uint32_t& r3, uint32_t a) {
    asm volatile("ldmatrix.sync.aligned.m8n8.x4.shared.b16 {%0,%1,%2,%3}, [%4];"
                 : "=r"(r0), "=r"(r1), "=r"(r2), "=r"(r3) : "r"(a));
}
__device__ __forceinline__ void ldsm4t(uint32_t& r0, uint32_t& r1, uint32_t& r2, uint32_t& r3, uint32_t a) {
    asm volatile("ldmatrix.sync.aligned.m8n8.x4.trans.shared.b16 {%0,%1,%2,%3}, [%4];"
                 : "=r"(r0), "=r"(r1), "=r"(r2), "=r"(r3) : "r"(a));
}
__device__ __forceinline__ void mma_f16(float* c, const uint32_t* a, const uint32_t* b) {
    asm volatile("mma.sync.aligned.m16n8k16.row.col.f32.f16.f16.f32 "
                 "{%0,%1,%2,%3},{%4,%5,%6,%7},{%8,%9},{%0,%1,%2,%3};"
                 : "+f"(c[0]), "+f"(c[1]), "+f"(c[2]), "+f"(c[3])
                 : "r"(a[0]), "r"(a[1]), "r"(a[2]), "r"(a[3]), "r"(b[0]), "r"(b[1]));
}
__device__ __forceinline__ uint32_t pkh2(float a, float b) {
    __half2 t = __floats2half2_rn(a, b);
    return *reinterpret_cast<uint32_t*>(&t);
}

constexpr int STG = 3;
constexpr int FFN_B = 41600;   // EPI2 FFN SMEM region size (bytes), 128-aligned

// ---------------------------------------------------------------------------
// Big GEMMs at the legacy-mma issue ceiling: MT=128, occ 2.
// EPI: 1 = sU, 2 = pre (+ fused FFN terms, SMEM-prefetched via cp.async)
// ---------------------------------------------------------------------------
template<int EPI, bool BT>
__global__ void __launch_bounds__(256, 2)
mma_gemm(const float* __restrict__ p0, float* __restrict__ outp, int K)
{
    constexpr int MT = 128;
    constexpr int TA = MT * 80;
    constexpr int TB = BT ? 32 * 272 : 128 * 80;
    constexpr int STAGE = TA + TB;
    constexpr int MI = 4;
    constexpr int FOFF = (EPI == 2) ? FFN_B : 0;

    extern __shared__ char sm[];
    const uint32_t smb = smem_u32(sm);
    const int tid = threadIdx.x, lane = tid & 31, w = tid >> 5;
    const int wm = w >> 2, wn = w & 3;

    int m0, n0, b = 0, s_base = 0;
    const __half *A, *Bg;
    int lda, ldn, bn0 = 0;
    if (EPI == 1) {
        m0 = blockIdx.y * MT; n0 = blockIdx.x * 128; lda = Tt;
        A = g_s16 + (size_t)m0 * Tt;
        Bg = g_U16; bn0 = n0; ldn = NU;
    } else {
        b = blockIdx.z;
        m0 = b * 4096 + blockIdx.y * MT; n0 = blockIdx.x * 128; lda = Tt;
        s_base = (m0 >> 4) & 255;
        A = g_sU + (size_t)m0 * Tt;
        Bg = g_e16 + (size_t)b * Ss * Tt + (size_t)n0 * Tt;
        ldn = Tt;
    }

    float acc[MI][4][4] = {};
    const int nk = K / 32;

    auto load_stage = [&](int st, int kb) {
        const uint32_t sb = smb + FOFF + st * STAGE;
        const int kc = kb * 32;
#pragma unroll
        for (int i = tid; i < MT * 4; i += 256) {
            const int row = i >> 2, ch = i & 3;
            cpa16(sb + row * 80 + ch * 16, A + (size_t)row * lda + kc + ch * 8);
        }
        if (BT) {
#pragma unroll
            for (int i = tid; i < 512; i += 256) {
                const int row = i >> 4, ch = i & 15;
                cpa16(sb + TA + row * 272 + ch * 16,
                      Bg + (size_t)(kc + row) * ldn + bn0 + ch * 8);
            }
        } else {
#pragma unroll
            for (int i = tid; i < 512; i += 256) {
                const int row = i >> 2, ch = i & 3;
                cpa16(sb + TA + row * 80 + ch * 16,
                      Bg + (size_t)row * ldn + kc + ch * 8);
            }
        }
    };

    // prologue: stage0 in group0; FFN prefetch rides with stage1 in group1
    load_stage(0, 0); CP_COMMIT();
    if (EPI == 2) {
        // ew0/ew1: 4096B each
        const __half* pe0 = g_prE16[0] + (b << 12) + (n0 << 4);
        const __half* pe1 = g_prE16[1] + (b << 12) + (n0 << 4);
        cpa16(smb + tid * 16,        pe0 + tid * 8);
        cpa16(smb + 4096 + tid * 16, pe1 + tid * 8);
        // sw0/sw1: 256B each
        if (tid < 16)                cpa16(smb + 8192 + tid * 16, g_prS16[0] + m0 + tid * 8);
        else if (tid < 32)           cpa16(smb + 8448 + (tid - 16) * 16, g_prS16[1] + m0 + (tid - 16) * 8);
        // wh: 8 chunks of 4096B (stride 8192B in global)
#pragma unroll
        for (int q = 0; q < 8; q++) {
            const int i = tid + q * 256;           // 0..2047
            const int chunk = i >> 8, within = i & 255;
            const __half* src = g_whWw16 + (((size_t)(s_base + chunk) * 256 + n0) << 4) + within * 8;
            cpa16(smb + 8704 + chunk * 4096 + within * 16, src);
        }
        // lin_b: 64B
        if (tid < 4) cpa16(smb + 41472 + tid * 16, p0 + tid * 4);
    }
    load_stage(1, 1); CP_COMMIT();

    for (int kb = 0; kb < nk; kb++) {
        CP_WAIT(STG - 2);
        __syncthreads();
        const int nx = kb + STG - 1;
        if (nx < nk) load_stage(nx % STG, nx);
        CP_COMMIT();

        const uint32_t base = smb + FOFF + (kb % STG) * STAGE;
        const uint32_t aB = base, bB = base + TA;
#pragma unroll
        for (int ks = 0; ks < 2; ks++) {
            const uint32_t aoff = (uint32_t)(wm * 64 + (lane & 15)) * 80
                                + ks * 32 + (lane >> 4) * 16;
            uint32_t Af[MI][4];
#pragma unroll
            for (int mi = 0; mi < MI; mi++)
                ldsm4(Af[mi][0], Af[mi][1], Af[mi][2], Af[mi][3], aB + aoff + mi * 16 * 80);
            uint32_t Bf[8];
            if (BT) {
                const uint32_t kk = (uint32_t)(ks * 16 + (lane & 15));
                const uint32_t bo = bB + kk * 272 + wn * 64 + ((lane >> 4) << 4);
                ldsm4t(Bf[0], Bf[1], Bf[2], Bf[3], bo);
                ldsm4t(Bf[4], Bf[5], Bf[6], Bf[7], bo + 32);
            } else {
                const uint32_t boff = (uint32_t)(wn * 32 + ((lane >> 4) << 3) + (lane & 7)) * 80
                                    + ks * 32 + ((lane >> 3) & 1) * 16;
                ldsm4(Bf[0], Bf[1], Bf[2], Bf[3], bB + boff);
                ldsm4(Bf[4], Bf[5], Bf[6], Bf[7], bB + boff + 16 * 80);
            }
#pragma unroll
            for (int mi = 0; mi < MI; mi++)
#pragma unroll
                for (int ni = 0; ni < 4; ni++)
                    mma_f16(acc[mi][ni], Af[mi], &Bf[2 * ni]);
        }
    }

    CP_WAIT(0);
    __syncthreads();
    float* Cp = reinterpret_cast<float*>(sm + FOFF);   // [128][132] row-major
#pragma unroll
    for (int mi = 0; mi < MI; mi++)
#pragma unroll
        for (int ni = 0; ni < 4; ni++)
#pragma unroll
            for (int r = 0; r < 4; r++) {
                const int ml = wm * 64 + mi * 16 + (lane >> 2) + ((r >> 1) ? 8 : 0);
                const int nl = wn * 32 + ni * 8 + 2 * (lane & 3) + (r & 1);
                Cp[ml * 132 + nl] = acc[mi][ni][r];
            }
    __syncthreads();

    if (EPI == 1) {
#pragma unroll
        for (int i = tid; i < 128 * 32; i += 256) {
            const int ml = i >> 5, j4 = (i & 31) << 2;
            float4 v = *reinterpret_cast<float4*>(&Cp[ml * 132 + j4]);
            const size_t o = (size_t)(m0 + ml) * NU + n0 + j4;
            *reinterpret_cast<uint2*>(&g_sU[o]) = make_uint2(pkh2(v.x, v.y), pkh2(v.z, v.w));
        }
    } else {
        const char* smc = sm;
#pragma unroll
        for (int sl_ = 0; sl_ < 8; sl_++) {
            const int s = s_base + sl_;
            float* obase = outp + (((size_t)(b * 256 + s)) * 256 + n0) * 16;
#pragma unroll
            for (int i = tid; i < 512; i += 256) {
                const int e = i >> 2, cq = (i & 3) << 2;
                const int mrow = sl_ * 16 + cq;
                float4 v;
                v.x = Cp[(mrow + 0) * 132 + e];
                v.y = Cp[(mrow + 1) * 132 + e];
                v.z = Cp[(mrow + 2) * 132 + e];
                v.w = Cp[(mrow + 3) * 132 + e];
                const int eo = (e * 16 + cq) * 2;
                float2 E0a = __half22float2(*(const __half2*)(smc + eo));
                float2 E0b = __half22float2(*(const __half2*)(smc + eo + 4));
                float2 E1a = __half22float2(*(const __half2*)(smc + 4096 + eo));
                float2 E1b = __half22float2(*(const __half2*)(smc + 4096 + eo + 4));
                float2 S0a = __half22float2(*(const __half2*)(smc + 8192 + mrow * 2));
                float2 S0b = __half22float2(*(const __half2*)(smc + 8192 + mrow * 2 + 4));
                float2 S1a = __half22float2(*(const __half2*)(smc + 8448 + mrow * 2));
                float2 S1b = __half22float2(*(const __half2*)(smc + 8448 + mrow * 2 + 4));
                const int wo = 8704 + sl_ * 4096 + eo;
                float2 Wa = __half22float2(*(const __half2*)(smc + wo));
                float2 Wb = __half22float2(*(const __half2*)(smc + wo + 4));
                float4 lb = *(const float4*)(smc + 41472 + cq * 4);
                v.x += E0a.x + E1a.x + Wa.x + S0a.x + S1a.x + lb.x;
                v.y += E0a.y + E1a.y + Wa.y + S0a.y + S1a.y + lb.y;
                v.z += E0b.x + E1b.x + Wb.x + S0b.x + S1b.x + lb.z;
                v.w += E0b.y + E1b.y + Wb.y + S0b.y + S1b.y + lb.w;
                *reinterpret_cast<float4*>(&obase[e * 16 + cq]) = v;
            }
        }
    }
}

// ---------------------------------------------------------------------------
// gemm0_fat: [0,128) s/e GEMM + fused proj ; [128,192) U convert ; [192,448) wh_proj
// ---------------------------------------------------------------------------
__global__ void __launch_bounds__(256, 3)
gemm0_fat(const float* __restrict__ sb, const float* __restrict__ eb,
          const float* __restrict__ linW, const float* __restrict__ U,
          const float* __restrict__ wh)
{
    extern __shared__ char sm[];
    const int bx = blockIdx.x;
    const int tid = threadIdx.x;

    if (bx >= 192) {                         // ---------------- wh_proj (fp16 out)
        float* tileS = reinterpret_cast<float*>(sm);
        float* WwS   = tileS + 64 * WDd;
        {
            float4 a = reinterpret_cast<const float4*>(linW + 2 * Tt * Cc)[tid];
            *reinterpret_cast<float4*>(&WwS[tid * 4]) = a;
        }
        const int c = tid & 15, pl0 = (tid >> 4) * 4;
        for (int it = 0; it < 4; it++) {
            const int p0 = (bx - 192) * 256 + it * 64;
            __syncthreads();
            const float4* src = reinterpret_cast<const float4*>(wh + (size_t)p0 * WDd);
#pragma unroll
            for (int l = 0; l < 4; l++) {
                float4 b = src[tid + l * 256];
                *reinterpret_cast<float4*>(&tileS[(tid + l * 256) * 4]) = b;
            }
            __syncthreads();
#pragma unroll
            for (int r = 0; r < 4; r++) {
                const int pl = pl0 + r;
                float acc = 0.f;
#pragma unroll
                for (int w = 0; w < WDd; w++)
                    acc += tileS[pl * WDd + w] * WwS[w * Cc + c];
                g_whWw16[(p0 + pl) * Cc + c] = __float2half(acc);
            }
        }
        return;
    }
    if (bx >= 128) {                         // ---------------- U convert
        const int base = (bx - 128) * 256 + tid;
#pragma unroll
        for (int it = 0; it < 16; it++) {
            const int j = base + it * 16384;
            float4 v = reinterpret_cast<const float4*>(U)[j];
            *reinterpret_cast<uint2*>(&g_U16[(size_t)j * 4]) =
                make_uint2(pkh2(v.x, v.y), pkh2(v.z, v.w));
        }
        return;
    }

    // ---------------- s/e projection GEMM, MT=32, BT
    constexpr int MT = 32;
    constexpr int TA = MT * 80;
    constexpr int TB = 32 * 272;
    constexpr int STAGE = TA + TB;

    const uint32_t smb = smem_u32(sm);
    const int lane = tid & 31, w = tid >> 5;
    const int wm = w >> 2, wn = w & 3;
    const int m0 = (bx >> 2) * MT, n0 = (bx & 3) * 128;
    const __half* A  = g_x + (size_t)m0 * HF;
    const __half* Bg = (n0 < 256) ? g_sW16 : g_eW16;
    const int bn0 = n0 & 255;
    constexpr int ldn = 256;

    float acc[1][4][4] = {};
    const int nk = HF / 32;   // 25

    auto load_stage = [&](int st, int kb) {
        const uint32_t sbm = smb + st * STAGE;
        const int kc = kb * 32;
#pragma unroll
        for (int i = tid; i < MT * 4; i += 256) {
            const int row = i >> 2, ch = i & 3;
            cpa16(sbm + row * 80 + ch * 16, A + (size_t)row * HF + kc + ch * 8);
        }
#pragma unroll
        for (int i = tid; i < 512; i += 256) {
            const int row = i >> 4, ch = i & 15;
            cpa16(sbm + TA + row * 272 + ch * 16,
                  Bg + (size_t)(kc + row) * ldn + bn0 + ch * 8);
        }
    };

#pragma unroll
    for (int s = 0; s < STG - 1; s++) {
        if (s < nk) load_stage(s, s);
        CP_COMMIT();
    }
    for (int kb = 0; kb < nk; kb++) {
        CP_WAIT(STG - 2);
        __syncthreads();
        const int nx = kb + STG - 1;
        if (nx < nk) load_stage(nx % STG, nx);
        CP_COMMIT();

        const uint32_t base = smb + (kb % STG) * STAGE;
        const uint32_t aB = base, bB = base + TA;
#pragma unroll
        for (int ks = 0; ks < 2; ks++) {
            const uint32_t aoff = (uint32_t)(wm * 16 + (lane & 15)) * 80
                                + ks * 32 + (lane >> 4) * 16;
            uint32_t Af[4];
            ldsm4(Af[0], Af[1], Af[2], Af[3], aB + aoff);
            uint32_t Bf[8];
            const uint32_t kk = (uint32_t)(ks * 16 + (lane & 15));
            const uint32_t bo = bB + kk * 272 + wn * 64 + ((lane >> 4) << 4);
            ldsm4t(Bf[0], Bf[1], Bf[2], Bf[3], bo);
            ldsm4t(Bf[4], Bf[5], Bf[6], Bf[7], bo + 32);
#pragma unroll
            for (int ni = 0; ni < 4; ni++)
                mma_f16(acc[0][ni], Af, &Bf[2 * ni]);
        }
    }

    CP_WAIT(0);
    __syncthreads();
    float* Cp = reinterpret_cast<float*>(sm);   // [32][132]
#pragma unroll
    for (int ni = 0; ni < 4; ni++)
#pragma unroll
        for (int r = 0; r < 4; r++) {
            const int ml = wm * 16 + (lane >> 2) + ((r >> 1) ? 8 : 0);
            const int nl = wn * 32 + ni * 8 + 2 * (lane & 3) + (r & 1);
            Cp[ml * 132 + nl] = acc[0][ni][r];
        }
    __syncthreads();

    const float* bias = (n0 < 256) ? sb : eb;
    __half* dst = (n0 < 256) ? g_s16 : g_e16;
    const int nc0 = n0 & 255;
#pragma unroll
    for (int i = tid; i < 32 * 32; i += 256) {
        const int ml = i >> 5, j4 = (i & 31) << 2;
        float4 v = *reinterpret_cast<float4*>(&Cp[ml * 132 + j4]);
        const int nc = nc0 + j4;
        v.x += bias[nc]; v.y += bias[nc + 1]; v.z += bias[nc + 2]; v.w += bias[nc + 3];
        *reinterpret_cast<float4*>(&Cp[ml * 132 + j4]) = v;
        const size_t o = (size_t)(m0 + ml) * Tt + nc;
        *reinterpret_cast<uint2*>(&dst[o]) = make_uint2(pkh2(v.x, v.y), pkh2(v.z, v.w));
    }
    float* Wp = Cp + 32 * 132;
#pragma unroll
    for (int i = tid; i < 512; i += 256)
        *reinterpret_cast<float4*>(&Wp[i * 4]) =
            reinterpret_cast<const float4*>(linW)[n0 * 4 + i];
    __syncthreads();
    __half* dpr = (n0 < 256) ? g_prS16[(n0 >> 7) & 1] : g_prE16[(n0 >> 7) & 1];
    const int c = lane & 15, th = lane >> 4;
    float ap[4] = {};
#pragma unroll 8
    for (int j = 0; j < 64; j++) {
        const int t = th * 64 + j;
        const float wv = Wp[t * Cc + c];
#pragma unroll
        for (int r = 0; r < 4; r++)
            ap[r] += Cp[(w * 4 + r) * 132 + t] * wv;
    }
#pragma unroll
    for (int r = 0; r < 4; r++)
        ap[r] += __shfl_xor_sync(0xffffffff, ap[r], 16);
    if (lane < 16) {
#pragma unroll
        for (int r = 0; r < 4; r++)
            dpr[(m0 + w * 4 + r) * Cc + c] = __float2half(ap[r]);
    }
}

// ---------------------------------------------------------------------------
__global__ void prep_xw(const float* __restrict__ fh, const float* __restrict__ fv,
                        const float* __restrict__ sW, const float* __restrict__ eW)
{
    const int i = blockIdx.x * 256 + threadIdx.x;
    float4 v;
    __half* dst;
    size_t o;
    if (i < 51200) {
        v = reinterpret_cast<const float4*>(sW)[i];
        dst = g_sW16; o = (size_t)i * 4;
    } else if (i < 102400) {
        const int j = i - 51200;
        v = reinterpret_cast<const float4*>(eW)[j];
        dst = g_eW16; o = (size_t)j * 4;
    } else {
        const int j = i - 102400;
        const int row = j / 200, c4 = j % 200;
        if (c4 < 192) v = reinterpret_cast<const float4*>(fh)[row * 192 + c4];
        else          v = reinterpret_cast<const float4*>(fv)[row * 8 + (c4 - 192)];
        dst = g_x; o = (size_t)row * HF + c4 * 4;
    }
    *reinterpret_cast<uint2*>(&dst[o]) = make_uint2(pkh2(v.x, v.y), pkh2(v.z, v.w));
}

// ------------------------------- launch
extern "C" void kernel_launch(void* const* d_in, const int* in_sizes, int n_in,
                              void* d_out, int out_size)
{
    const float* fh   = (const float*)d_in[0];
    const float* fv   = (const float*)d_in[1];
    const float* sW   = (const float*)d_in[2];
    const float* sb   = (const float*)d_in[3];
    const float* eW   = (const float*)d_in[4];
    const float* eb   = (const float*)d_in[5];
    const float* U    = (const float*)d_in[6];
    const float* wh   = (const float*)d_in[7];
    const float* linW = (const float*)d_in[8];
    const float* linb = (const float*)d_in[9];
    float* out = (float*)d_out;

    constexpr int SMEM_G0 = STG * 11264;                     // 33792 >= 25088 staging
    constexpr int SMEM_G1 = 128 * 132 * 4;                   // 67584 >= 3*18944=56832
    constexpr int SMEM_G2 = FFN_B + 128 * 132 * 4;           // 109184 >= 41600+61440

    cudaFuncSetAttribute(gemm0_fat,          cudaFuncAttributeMaxDynamicSharedMemorySize, SMEM_G0);
    cudaFuncSetAttribute(mma_gemm<1, true>,  cudaFuncAttributeMaxDynamicSharedMemorySize, SMEM_G1);
    cudaFuncSetAttribute(mma_gemm<2, false>, cudaFuncAttributeMaxDynamicSharedMemorySize, SMEM_G2);

    prep_xw<<<1200, 256>>>(fh, fv, sW, eW);
    gemm0_fat<<<448, 256, SMEM_G0>>>(sb, eb, linW, U, wh);
    mma_gemm<1, true><<<dim3(32, 8), 256, SMEM_G1>>>(nullptr, nullptr, Tt);   // sU
    mma_gemm<2, false><<<dim3(2, 32, 4), 256, SMEM_G2>>>(linb, out, Tt);      // pre
}

// round 17
// speedup vs baseline: 1.1495x; 1.0434x over previous
#include <cuda_runtime.h>
#include <cuda_fp16.h>
#include <cstdint>

#define Hh 768
#define Ff 32
#define Tt 256
#define HF 800
#define BSr 1024
#define NU 4096
#define Cc 16
#define WDd 64
#define Ss 256

// ------------------------------- scratch (device globals)
__device__ __align__(256) __half g_x   [BSr * HF];
__device__ __align__(256) __half g_sW16[HF * Tt];
__device__ __align__(256) __half g_eW16[HF * Tt];
__device__ __align__(256) __half g_U16 [Tt * NU];
__device__ __align__(256) __half g_s16 [BSr * Tt];
__device__ __align__(256) __half g_e16 [BSr * Tt];
__device__ __align__(256) __half g_sU  [BSr * NU];
__device__ __align__(256) __half g_prS16[2][BSr * Cc];
__device__ __align__(256) __half g_prE16[2][BSr * Cc];
__device__ __align__(256) __half g_whWw16[Ss * Ss * Cc];
__device__ unsigned g_bandCnt[8];

// ------------------------------- PTX helpers
__device__ __forceinline__ uint32_t smem_u32(const void* p) {
    uint32_t a;
    asm("{ .reg .u64 t; cvta.to.shared.u64 t, %1; cvt.u32.u64 %0, t; }" : "=r"(a) : "l"(p));
    return a;
}
__device__ __forceinline__ void cpa16(uint32_t dst, const void* src) {
    asm volatile("cp.async.cg.shared.global [%0], [%1], 16;" :: "r"(dst), "l"(src));
}
#define CP_COMMIT() asm volatile("cp.async.commit_group;" ::: "memory")
#define CP_WAIT(n)  asm volatile("cp.async.wait_group %0;" :: "n"(n) : "memory")

__device__ __forceinline__ void ldsm4(uint32_t& r0, uint32_t& r1, uint32_t& r2, uint32_t& r3, uint32_t a) {
    asm volatile("ldmatrix.sync.aligned.m8n8.x4.shared.b16 {%0,%1,%2,%3}, [%4];"
                 : "=r"(r0), "=r"(r1), "=r"(r2), "=r"(r3) : "r"(a));
}
__device__ __forceinline__ void ldsm4t(uint32_t& r0, uint32_t& r1, uint32_t& r2, uint32_t& r3, uint32_t a) {
    asm volatile("ldmatrix.sync.aligned.m8n8.x4.trans.shared.b16 {%0,%1,%2,%3}, [%4];"
                 : "=r"(r0), "=r"(r1), "=r"(r2), "=r"(r3) : "r"(a));
}
__device__ __forceinline__ void mma_f16(float* c, const uint32_t* a, const uint32_t* b) {
    asm volatile("mma.sync.aligned.m16n8k16.row.col.f32.f16.f16.f32 "
                 "{%0,%1,%2,%3},{%4,%5,%6,%7},{%8,%9},{%0,%1,%2,%3};"
                 : "+f"(c[0]), "+f"(c[1]), "+f"(c[2]), "+f"(c[3])
                 : "r"(a[0]), "r"(a[1]), "r"(a[2]), "r"(a[3]), "r"(b[0]), "r"(b[1]));
}
__device__ __forceinline__ uint32_t pkh2(float a, float b) {
    __half2 t = __floats2half2_rn(a, b);
    return *reinterpret_cast<uint32_t*>(&t);
}

constexpr int STG = 3;
constexpr int FFN_B = 41600;

// ---------------------------------------------------------------------------
// gemm12: fused sU-GEMM (CTAs [0,256)) + pre-GEMM (CTAs [256,512)), with
// band-granular spin dependency on g_bandCnt (reset each replay by gemm0_fat).
// ---------------------------------------------------------------------------
__global__ void __launch_bounds__(256, 2)
gemm12(const float* __restrict__ linb, float* __restrict__ outp)
{
    extern __shared__ char sm[];
    const uint32_t smb = smem_u32(sm);
    const int tid = threadIdx.x, lane = tid & 31, w = tid >> 5;
    const int wm = w >> 2, wn = w & 3;
    constexpr int MT = 128, TA = MT * 80, MI = 4;
    constexpr int K = Tt, nk = K / 32;

    if (blockIdx.x < 256) {
        // ==================== gemm1: sU = s16 @ U16 (BT), band = y ====================
        constexpr int TB = 32 * 272;
        constexpr int STAGE = TA + TB;
        const int x = blockIdx.x & 31, y = blockIdx.x >> 5;
        const int m0 = y * 128, n0 = x * 128;
        const __half* A  = g_s16 + (size_t)m0 * Tt;
        const __half* Bg = g_U16;
        const int bn0 = n0;

        float acc[MI][4][4] = {};
        auto load_stage = [&](int st, int kb) {
            const uint32_t sb = smb + st * STAGE;
            const int kc = kb * 32;
#pragma unroll
            for (int i = tid; i < MT * 4; i += 256) {
                const int row = i >> 2, ch = i & 3;
                cpa16(sb + row * 80 + ch * 16, A + (size_t)row * Tt + kc + ch * 8);
            }
#pragma unroll
            for (int i = tid; i < 512; i += 256) {
                const int row = i >> 4, ch = i & 15;
                cpa16(sb + TA + row * 272 + ch * 16,
                      Bg + (size_t)(kc + row) * NU + bn0 + ch * 8);
            }
        };
        load_stage(0, 0); CP_COMMIT();
        load_stage(1, 1); CP_COMMIT();
        for (int kb = 0; kb < nk; kb++) {
            CP_WAIT(1);
            __syncthreads();
            const int nx = kb + STG - 1;
            if (nx < nk) load_stage(nx % STG, nx);
            CP_COMMIT();
            const uint32_t base = smb + (kb % STG) * STAGE;
            const uint32_t aB = base, bB = base + TA;
#pragma unroll
            for (int ks = 0; ks < 2; ks++) {
                const uint32_t aoff = (uint32_t)(wm * 64 + (lane & 15)) * 80
                                    + ks * 32 + (lane >> 4) * 16;
                uint32_t Af[MI][4];
#pragma unroll
                for (int mi = 0; mi < MI; mi++)
                    ldsm4(Af[mi][0], Af[mi][1], Af[mi][2], Af[mi][3], aB + aoff + mi * 16 * 80);
                uint32_t Bf[8];
                const uint32_t kk = (uint32_t)(ks * 16 + (lane & 15));
                const uint32_t bo = bB + kk * 272 + wn * 64 + ((lane >> 4) << 4);
                ldsm4t(Bf[0], Bf[1], Bf[2], Bf[3], bo);
                ldsm4t(Bf[4], Bf[5], Bf[6], Bf[7], bo + 32);
#pragma unroll
                for (int mi = 0; mi < MI; mi++)
#pragma unroll
                    for (int ni = 0; ni < 4; ni++)
                        mma_f16(acc[mi][ni], Af[mi], &Bf[2 * ni]);
            }
        }
        __syncthreads();
        float* Cp = reinterpret_cast<float*>(sm);   // [128][132]
#pragma unroll
        for (int mi = 0; mi < MI; mi++)
#pragma unroll
            for (int ni = 0; ni < 4; ni++)
#pragma unroll
                for (int r = 0; r < 4; r++) {
                    const int ml = wm * 64 + mi * 16 + (lane >> 2) + ((r >> 1) ? 8 : 0);
                    const int nl = wn * 32 + ni * 8 + 2 * (lane & 3) + (r & 1);
                    Cp[ml * 132 + nl] = acc[mi][ni][r];
                }
        __syncthreads();
#pragma unroll
        for (int i = tid; i < 128 * 32; i += 256) {
            const int ml = i >> 5, j4 = (i & 31) << 2;
            float4 v = *reinterpret_cast<float4*>(&Cp[ml * 132 + j4]);
            const size_t o = (size_t)(m0 + ml) * NU + n0 + j4;
            *reinterpret_cast<uint2*>(&g_sU[o]) = make_uint2(pkh2(v.x, v.y), pkh2(v.z, v.w));
        }
        __threadfence();
        __syncthreads();
        if (tid == 0) atomicAdd(&g_bandCnt[y], 1u);
    } else {
        // ==================== gemm2: pre = sU @ e16^T (+FFN), waits on band ====================
        constexpr int TB = 128 * 80;
        constexpr int STAGE = TA + TB;
        const int j = blockIdx.x - 256;
        const int b = j >> 6, y = (j >> 1) & 31, x = j & 1;
        const int m0 = b * 4096 + y * 128, n0 = x * 128;
        const int s_base = (m0 >> 4) & 255;
        const int band = b * 2 + (y >> 4);
        const __half* A  = g_sU + (size_t)m0 * Tt;
        const __half* Bg = g_e16 + (size_t)b * Ss * Tt + (size_t)n0 * Tt;

        // FFN prefetch: own commit group, independent of gemm1
        {
            const __half* pe0 = g_prE16[0] + (b << 12) + (n0 << 4);
            const __half* pe1 = g_prE16[1] + (b << 12) + (n0 << 4);
            cpa16(smb + tid * 16,        pe0 + tid * 8);
            cpa16(smb + 4096 + tid * 16, pe1 + tid * 8);
            if (tid < 16)      cpa16(smb + 8192 + tid * 16, g_prS16[0] + m0 + tid * 8);
            else if (tid < 32) cpa16(smb + 8448 + (tid - 16) * 16, g_prS16[1] + m0 + (tid - 16) * 8);
#pragma unroll
            for (int q = 0; q < 8; q++) {
                const int i = tid + q * 256;
                const int chunk = i >> 8, within = i & 255;
                const __half* src = g_whWw16 + (((size_t)(s_base + chunk) * 256 + n0) << 4) + within * 8;
                cpa16(smb + 8704 + chunk * 4096 + within * 16, src);
            }
            if (tid < 4) cpa16(smb + 41472 + tid * 16, linb + tid * 4);
        }
        CP_COMMIT();

        // wait for producer band
        if (tid == 0) {
            volatile unsigned* c = (volatile unsigned*)&g_bandCnt[band];
            while (*c < 32u) {}
            __threadfence();
        }
        __syncthreads();

        float acc[MI][4][4] = {};
        auto load_stage = [&](int st, int kb) {
            const uint32_t sb = smb + FFN_B + st * STAGE;
            const int kc = kb * 32;
#pragma unroll
            for (int i = tid; i < MT * 4; i += 256) {
                const int row = i >> 2, ch = i & 3;
                cpa16(sb + row * 80 + ch * 16, A + (size_t)row * Tt + kc + ch * 8);
            }
#pragma unroll
            for (int i = tid; i < 512; i += 256) {
                const int row = i >> 2, ch = i & 3;
                cpa16(sb + TA + row * 80 + ch * 16,
                      Bg + (size_t)row * Tt + kc + ch * 8);
            }
        };
        load_stage(0, 0); CP_COMMIT();
        load_stage(1, 1); CP_COMMIT();
        for (int kb = 0; kb < nk; kb++) {
            CP_WAIT(1);
            __syncthreads();
            const int nx = kb + STG - 1;
            if (nx < nk) load_stage(nx % STG, nx);
            CP_COMMIT();
            const uint32_t base = smb + FFN_B + (kb % STG) * STAGE;
            const uint32_t aB = base, bB = base + TA;
#pragma unroll
            for (int ks = 0; ks < 2; ks++) {
                const uint32_t aoff = (uint32_t)(wm * 64 + (lane & 15)) * 80
                                    + ks * 32 + (lane >> 4) * 16;
                uint32_t Af[MI][4];
#pragma unroll
                for (int mi = 0; mi < MI; mi++)
                    ldsm4(Af[mi][0], Af[mi][1], Af[mi][2], Af[mi][3], aB + aoff + mi * 16 * 80);
                uint32_t Bf[8];
                const uint32_t boff = (uint32_t)(wn * 32 + ((lane >> 4) << 3) + (lane & 7)) * 80
                                    + ks * 32 + ((lane >> 3) & 1) * 16;
                ldsm4(Bf[0], Bf[1], Bf[2], Bf[3], bB + boff);
                ldsm4(Bf[4], Bf[5], Bf[6], Bf[7], bB + boff + 16 * 80);
#pragma unroll
                for (int mi = 0; mi < MI; mi++)
#pragma unroll
                    for (int ni = 0; ni < 4; ni++)
                        mma_f16(acc[mi][ni], Af[mi], &Bf[2 * ni]);
            }
        }
        CP_WAIT(0);
        __syncthreads();
        float* Cp = reinterpret_cast<float*>(sm + FFN_B);   // [128][132]
#pragma unroll
        for (int mi = 0; mi < MI; mi++)
#pragma unroll
            for (int ni = 0; ni < 4; ni++)
#pragma unroll
                for (int r = 0; r < 4; r++) {
                    const int ml = wm * 64 + mi * 16 + (lane >> 2) + ((r >> 1) ? 8 : 0);
                    const int nl = wn * 32 + ni * 8 + 2 * (lane & 3) + (r & 1);
                    Cp[ml * 132 + nl] = acc[mi][ni][r];
                }
        __syncthreads();
        const char* smc = sm;
#pragma unroll
        for (int sl_ = 0; sl_ < 8; sl_++) {
            const int s = s_base + sl_;
            float* obase = outp + (((size_t)(b * 256 + s)) * 256 + n0) * 16;
#pragma unroll
            for (int i = tid; i < 512; i += 256) {
                const int e = i >> 2, cq = (i & 3) << 2;
                const int mrow = sl_ * 16 + cq;
                float4 v;
                v.x = Cp[(mrow + 0) * 132 + e];
                v.y = Cp[(mrow + 1) * 132 + e];
                v.z = Cp[(mrow + 2) * 132 + e];
                v.w = Cp[(mrow + 3) * 132 + e];
                const int eo = (e * 16 + cq) * 2;
                float2 E0a = __half22float2(*(const __half2*)(smc + eo));
                float2 E0b = __half22float2(*(const __half2*)(smc + eo + 4));
                float2 E1a = __half22float2(*(const __half2*)(smc + 4096 + eo));
                float2 E1b = __half22float2(*(const __half2*)(smc + 4096 + eo + 4));
                float2 S0a = __half22float2(*(const __half2*)(smc + 8192 + mrow * 2));
                float2 S0b = __half22float2(*(const __half2*)(smc + 8192 + mrow * 2 + 4));
                float2 S1a = __half22float2(*(const __half2*)(smc + 8448 + mrow * 2));
                float2 S1b = __half22float2(*(const __half2*)(smc + 8448 + mrow * 2 + 4));
                const int wo = 8704 + sl_ * 4096 + eo;
                float2 Wa = __half22float2(*(const __half2*)(smc + wo));
                float2 Wb = __half22float2(*(const __half2*)(smc + wo + 4));
                float4 lb = *(const float4*)(smc + 41472 + cq * 4);
                v.x += E0a.x + E1a.x + Wa.x + S0a.x + S1a.x + lb.x;
                v.y += E0a.y + E1a.y + Wa.y + S0a.y + S1a.y + lb.y;
                v.z += E0b.x + E1b.x + Wb.x + S0b.x + S1b.x + lb.z;
                v.w += E0b.y + E1b.y + Wb.y + S0b.y + S1b.y + lb.w;
                *reinterpret_cast<float4*>(&obase[e * 16 + cq]) = v;
            }
        }
    }
}

// ---------------------------------------------------------------------------
// gemm0_fat: [0,128) s/e GEMM + fused proj ; [128,192) U convert ; [192,448) wh_proj
// block 0 thread 0..7 also resets band counters for gemm12.
// ---------------------------------------------------------------------------
__global__ void __launch_bounds__(256, 3)
gemm0_fat(const float* __restrict__ sb, const float* __restrict__ eb,
          const float* __restrict__ linW, const float* __restrict__ U,
          const float* __restrict__ wh)
{
    extern __shared__ char sm[];
    const int bx = blockIdx.x;
    const int tid = threadIdx.x;

    if (bx == 0 && tid < 8) g_bandCnt[tid] = 0;

    if (bx >= 192) {                         // ---------------- wh_proj (fp16 out)
        float* tileS = reinterpret_cast<float*>(sm);
        float* WwS   = tileS + 64 * WDd;
        {
            float4 a = reinterpret_cast<const float4*>(linW + 2 * Tt * Cc)[tid];
            *reinterpret_cast<float4*>(&WwS[tid * 4]) = a;
        }
        const int c = tid & 15, pl0 = (tid >> 4) * 4;
        for (int it = 0; it < 4; it++) {
            const int p0 = (bx - 192) * 256 + it * 64;
            __syncthreads();
            const float4* src = reinterpret_cast<const float4*>(wh + (size_t)p0 * WDd);
#pragma unroll
            for (int l = 0; l < 4; l++) {
                float4 b = src[tid + l * 256];
                *reinterpret_cast<float4*>(&tileS[(tid + l * 256) * 4]) = b;
            }
            __syncthreads();
#pragma unroll
            for (int r = 0; r < 4; r++) {
                const int pl = pl0 + r;
                float acc = 0.f;
#pragma unroll
                for (int w = 0; w < WDd; w++)
                    acc += tileS[pl * WDd + w] * WwS[w * Cc + c];
                g_whWw16[(p0 + pl) * Cc + c] = __float2half(acc);
            }
        }
        return;
    }
    if (bx >= 128) {                         // ---------------- U convert
        const int base = (bx - 128) * 256 + tid;
#pragma unroll
        for (int it = 0; it < 16; it++) {
            const int j = base + it * 16384;
            float4 v = reinterpret_cast<const float4*>(U)[j];
            *reinterpret_cast<uint2*>(&g_U16[(size_t)j * 4]) =
                make_uint2(pkh2(v.x, v.y), pkh2(v.z, v.w));
        }
        return;
    }

    // ---------------- s/e projection GEMM, MT=32, BT
    constexpr int MT = 32;
    constexpr int TA = MT * 80;
    constexpr int TB = 32 * 272;
    constexpr int STAGE = TA + TB;

    const uint32_t smb = smem_u32(sm);
    const int lane = tid & 31, w = tid >> 5;
    const int wm = w >> 2, wn = w & 3;
    const int m0 = (bx >> 2) * MT, n0 = (bx & 3) * 128;
    const __half* A  = g_x + (size_t)m0 * HF;
    const __half* Bg = (n0 < 256) ? g_sW16 : g_eW16;
    const int bn0 = n0 & 255;
    constexpr int ldn = 256;

    float acc[1][4][4] = {};
    const int nk = HF / 32;   // 25

    auto load_stage = [&](int st, int kb) {
        const uint32_t sbm = smb + st * STAGE;
        const int kc = kb * 32;
#pragma unroll
        for (int i = tid; i < MT * 4; i += 256) {
            const int row = i >> 2, ch = i & 3;
            cpa16(sbm + row * 80 + ch * 16, A + (size_t)row * HF + kc + ch * 8);
        }
#pragma unroll
        for (int i = tid; i < 512; i += 256) {
            const int row = i >> 4, ch = i & 15;
            cpa16(sbm + TA + row * 272 + ch * 16,
                  Bg + (size_t)(kc + row) * ldn + bn0 + ch * 8);
        }
    };

#pragma unroll
    for (int s = 0; s < STG - 1; s++) {
        if (s < nk) load_stage(s, s);
        CP_COMMIT();
    }
    for (int kb = 0; kb < nk; kb++) {
        CP_WAIT(STG - 2);
        __syncthreads();
        const int nx = kb + STG - 1;
        if (nx < nk) load_stage(nx % STG, nx);
        CP_COMMIT();

        const uint32_t base = smb + (kb % STG) * STAGE;
        const uint32_t aB = base, bB = base + TA;
#pragma unroll
        for (int ks = 0; ks < 2; ks++) {
            const uint32_t aoff = (uint32_t)(wm * 16 + (lane & 15)) * 80
                                + ks * 32 + (lane >> 4) * 16;
            uint32_t Af[4];
            ldsm4(Af[0], Af[1], Af[2], Af[3], aB + aoff);
            uint32_t Bf[8];
            const uint32_t kk = (uint32_t)(ks * 16 + (lane & 15));
            const uint32_t bo = bB + kk * 272 + wn * 64 + ((lane >> 4) << 4);
            ldsm4t(Bf[0], Bf[1], Bf[2], Bf[3], bo);
            ldsm4t(Bf[4], Bf[5], Bf[6], Bf[7], bo + 32);
#pragma unroll
            for (int ni = 0; ni < 4; ni++)
                mma_f16(acc[0][ni], Af, &Bf[2 * ni]);
        }
    }

    CP_WAIT(0);
    __syncthreads();
    float* Cp = reinterpret_cast<float*>(sm);   // [32][132]
#pragma unroll
    for (int ni = 0; ni < 4; ni++)
#pragma unroll
        for (int r = 0; r < 4; r++) {
            const int ml = wm * 16 + (lane >> 2) + ((r >> 1) ? 8 : 0);
            const int nl = wn * 32 + ni * 8 + 2 * (lane & 3) + (r & 1);
            Cp[ml * 132 + nl] = acc[0][ni][r];
        }
    __syncthreads();

    const float* bias = (n0 < 256) ? sb : eb;
    __half* dst = (n0 < 256) ? g_s16 : g_e16;
    const int nc0 = n0 & 255;
#pragma unroll
    for (int i = tid; i < 32 * 32; i += 256) {
        const int ml = i >> 5, j4 = (i & 31) << 2;
        float4 v = *reinterpret_cast<float4*>(&Cp[ml * 132 + j4]);
        const int nc = nc0 + j4;
        v.x += bias[nc]; v.y += bias[nc + 1]; v.z += bias[nc + 2]; v.w += bias[nc + 3];
        *reinterpret_cast<float4*>(&Cp[ml * 132 + j4]) = v;
        const size_t o = (size_t)(m0 + ml) * Tt + nc;
        *reinterpret_cast<uint2*>(&dst[o]) = make_uint2(pkh2(v.x, v.y), pkh2(v.z, v.w));
    }
    float* Wp = Cp + 32 * 132;
#pragma unroll
    for (int i = tid; i < 512; i += 256)
        *reinterpret_cast<float4*>(&Wp[i * 4]) =
            reinterpret_cast<const float4*>(linW)[n0 * 4 + i];
    __syncthreads();
    __half* dpr = (n0 < 256) ? g_prS16[(n0 >> 7) & 1] : g_prE16[(n0 >> 7) & 1];
    const int c = lane & 15, th = lane >> 4;
    float ap[4] = {};
#pragma unroll 8
    for (int j = 0; j < 64; j++) {
        const int t = th * 64 + j;
        const float wv = Wp[t * Cc + c];
#pragma unroll
        for (int r = 0; r < 4; r++)
            ap[r] += Cp[(w * 4 + r) * 132 + t] * wv;
    }
#pragma unroll
    for (int r = 0; r < 4; r++)
        ap[r] += __shfl_xor_sync(0xffffffff, ap[r], 16);
    if (lane < 16) {
#pragma unroll
        for (int r = 0; r < 4; r++)
            dpr[(m0 + w * 4 + r) * Cc + c] = __float2half(ap[r]);
    }
}

// ---------------------------------------------------------------------------
__global__ void prep_xw(const float* __restrict__ fh, const float* __restrict__ fv,
                        const float* __restrict__ sW, const float* __restrict__ eW)
{
    const int i = blockIdx.x * 256 + threadIdx.x;
    float4 v;
    __half* dst;
    size_t o;
    if (i < 51200) {
        v = reinterpret_cast<const float4*>(sW)[i];
        dst = g_sW16; o = (size_t)i * 4;
    } else if (i < 102400) {
        const int j = i - 51200;
        v = reinterpret_cast<const float4*>(eW)[j];
        dst = g_eW16; o = (size_t)j * 4;
    } else {
        const int j = i - 102400;
        const int row = j / 200, c4 = j % 200;
        if (c4 < 192) v = reinterpret_cast<const float4*>(fh)[row * 192 + c4];
        else          v = reinterpret_cast<const float4*>(fv)[row * 8 + (c4 - 192)];
        dst = g_x; o = (size_t)row * HF + c4 * 4;
    }
    *reinterpret_cast<uint2*>(&dst[o]) = make_uint2(pkh2(v.x, v.y), pkh2(v.z, v.w));
}

// ------------------------------- launch
extern "C" void kernel_launch(void* const* d_in, const int* in_sizes, int n_in,
                              void* d_out, int out_size)
{
    const float* fh   = (const float*)d_in[0];
    const float* fv   = (const float*)d_in[1];
    const float* sW   = (const float*)d_in[2];
    const float* sb   = (const float*)d_in[3];
    const float* eW   = (const float*)d_in[4];
    const float* eb   = (const float*)d_in[5];
    const float* U    = (const float*)d_in[6];
    const float* wh   = (const float*)d_in[7];
    const float* linW = (const float*)d_in[8];
    const float* linb = (const float*)d_in[9];
    float* out = (float*)d_out;

    constexpr int SMEM_G0  = STG * 11264;                    // 33792
    constexpr int SMEM_G12 = FFN_B + 128 * 132 * 4;          // 109184 (covers both roles)

    cudaFuncSetAttribute(gemm0_fat, cudaFuncAttributeMaxDynamicSharedMemorySize, SMEM_G0);
    cudaFuncSetAttribute(gemm12,    cudaFuncAttributeMaxDynamicSharedMemorySize, SMEM_G12);

    prep_xw<<<1200, 256>>>(fh, fv, sW, eW);
    gemm0_fat<<<448, 256, SMEM_G0>>>(sb, eb, linW, U, wh);
    gemm12<<<512, 256, SMEM_G12>>>(linb, out);
}